// round 14
// baseline (speedup 1.0000x reference)
#include <cuda_runtime.h>
#include <cuda_fp16.h>
#include <stdint.h>
#include <math.h>

#define Hd 1024
#define Sd 2048
#define Bd 16
#define Ad 8
#define BS (Bd * Sd)          // 32768 rows

#define NCTA 296              // 148 SMs x 2, all resident -> spins are safe
#define NUNIT 2048            // 256 m-tiles x 8 n-tiles
#define BM 128
#define BN 128
#define BKg 32
#define STG 4
#define LDT 80                          // padded row pitch bytes
#define A_SZ (BM * LDT)                 // 10240
#define STAGE_BYTES (2 * A_SZ)          // 20480
#define SMEM_TOTAL (STG * STAGE_BYTES)  // 81920 (x2 CTAs = 164KB/SM)

#define WROWS 4736                      // rows per wave (37 m-tiles x 128)

// ---------------------------------------------------------------------------
__device__ __half g_Xh[(size_t)BS * Hd];        // 64 MB fp16 X (filled in-GEMM)
__device__ __half g_Wt[(size_t)Hd * Hd];        // W1^T: [N][K], fp16
__device__ float g_cvec[Bd * Hd];
__device__ float g_part[16 * BS];               // 2 MB partial scores
__device__ float g_weights[Bd * Sd];
__device__ int   g_mcnt[256];                   // per-m-tile converted-row count

// ---------------------------------------------------------------------------
__device__ __forceinline__ uint32_t smem_u32(const void* p) {
    uint32_t a;
    asm("{ .reg .u64 t; cvta.to.shared.u64 t, %1; cvt.u32.u64 %0, t; }" : "=r"(a) : "l"(p));
    return a;
}
__device__ __forceinline__ void cpa16(uint32_t dst, const void* src) {
    asm volatile("cp.async.cg.shared.global [%0], [%1], 16;" :: "r"(dst), "l"(src));
}
__device__ __forceinline__ void cpa_commit() {
    asm volatile("cp.async.commit_group;" ::: "memory");
}
#define CPA_WAIT2() asm volatile("cp.async.wait_group 2;" ::: "memory")
#define LDSM4(r, addr)                                                        \
    asm volatile("ldmatrix.sync.aligned.m8n8.x4.shared.b16 {%0,%1,%2,%3}, [%4];" \
        : "=r"((r)[0]), "=r"((r)[1]), "=r"((r)[2]), "=r"((r)[3]) : "r"(addr))
__device__ __forceinline__ void mma16816h(uint32_t* d, const uint32_t* a,
                                          uint32_t b0, uint32_t b1) {
    asm volatile(
        "mma.sync.aligned.m16n8k16.row.col.f16.f16.f16.f16 "
        "{%0,%1}, {%2,%3,%4,%5}, {%6,%7}, {%0,%1};"
        : "+r"(d[0]), "+r"(d[1])
        : "r"(a[0]), "r"(a[1]), "r"(a[2]), "r"(a[3]), "r"(b0), "r"(b1));
}
__device__ __forceinline__ float fast_tanh(float x) {
    float y;
    asm("tanh.approx.f32 %0, %1;" : "=f"(y) : "f"(x));
    return y;
}
__device__ __forceinline__ uint2 cvt8(const float4 v) {
    __half2 lo = __floats2half2_rn(v.x, v.y);
    __half2 hi = __floats2half2_rn(v.z, v.w);
    uint2 r;
    r.x = *reinterpret_cast<const uint32_t*>(&lo);
    r.y = *reinterpret_cast<const uint32_t*>(&hi);
    return r;
}

// ---------------------------------------------------------------------------
// Prep: [0,1024) transpose W1 -> fp16 K-major; [1024,1088) cvec; 1088 zero.
// ---------------------------------------------------------------------------
__global__ void prep_kernel(const float* __restrict__ W,
                            const float* __restrict__ aspect,
                            const float* __restrict__ bias) {
    int bi = blockIdx.x, tid = threadIdx.x;
    if (bi < 1024) {
        __shared__ float t[32][33];
        int n0 = (bi & 31) * 32, k0 = (bi >> 5) * 32;
        int tx = tid & 31, ty = tid >> 5;            // 32 x 8
        #pragma unroll
        for (int i = 0; i < 32; i += 8)
            t[ty + i][tx] = W[(size_t)(k0 + ty + i) * Hd + n0 + tx];
        __syncthreads();
        #pragma unroll
        for (int i = 0; i < 32; i += 8)
            g_Wt[(size_t)(n0 + ty + i) * Hd + k0 + tx] = __float2half(t[tx][ty + i]);
    } else if (bi < 1088) {
        __shared__ float asp[Hd];
        int q = bi - 1024;
        int b = q & 15, hb = q >> 4;
        for (int k = tid; k < Hd; k += 256) {
            float s = 0.f;
            #pragma unroll
            for (int a = 0; a < Ad; ++a)
                s += aspect[(size_t)(b * Ad + a) * Hd + k];
            asp[k] = s * (1.0f / Ad);
        }
        __syncthreads();
        int h = hb * 256 + tid;
        float acc = bias[h];
        const float* Wp = W + (size_t)Hd * Hd + h;
        #pragma unroll 8
        for (int k = 0; k < Hd; ++k)
            acc = fmaf(asp[k], Wp[(size_t)k * Hd], acc);
        g_cvec[b * Hd + h] = acc;
    } else {
        if (tid < 256) g_mcnt[tid] = 0;
    }
}

// ---------------------------------------------------------------------------
// Persistent fused GEMM + tanh + v-dot -> g_part, with pipelined in-kernel
// fp32->fp16 conversion: prologue converts waves 0-1; wave w converts w+2.
// Per-m-tile readiness counters; LDG prefetched one chunk ahead of its STG.
// Core = R8: unit 128x128xK1024, 8 warps 4(M)x2(N), 4-stage cp.async.
// ---------------------------------------------------------------------------
__global__ void __launch_bounds__(256, 2)
gemm_score_mma(const float4* __restrict__ tok4, const float* __restrict__ v) {
    extern __shared__ char smem[];
    uint32_t sb = smem_u32(smem);

    int tid = threadIdx.x, lane = tid & 31, wid = tid >> 5;
    int warpM = wid & 3, warpN = wid >> 2;
    int c = blockIdx.x;
    uint2* Xh4 = reinterpret_cast<uint2*>(g_Xh);

    // --- prologue: convert waves 0 and 1 (slices c and c+296) ---
    {
        #pragma unroll
        for (int s = 0; s < 2; ++s) {
            int base4 = (c + s * 296) * 4096;   // 16 rows x 256 float4
            for (int t = tid; t < 4096; t += 256)
                Xh4[base4 + t] = cvt8(tok4[base4 + t]);
        }
        __threadfence();
        __syncthreads();
        if (tid == 0) {
            atomicAdd(&g_mcnt[c >> 3], 16);
            atomicAdd(&g_mcnt[(c + 296) >> 3], 16);
        }
    }

    uint32_t aoff[2], boff[4];
    #pragma unroll
    for (int mt = 0; mt < 2; ++mt) {
        int r = warpM * 32 + mt * 16 + ((lane >> 3) & 1) * 8 + (lane & 7);
        aoff[mt] = r * LDT + (lane >> 4) * 16;
    }
    #pragma unroll
    for (int jp = 0; jp < 4; ++jp) {
        int n = warpN * 64 + (jp * 2 + (lane >> 4)) * 8 + (lane & 7);
        boff[jp] = A_SZ + n * LDT + ((lane >> 3) & 1) * 16;
    }

    int lr  = tid >> 2;
    int lc  = (tid & 3) * 16;
    int lck = (tid & 3) * 8;

    int w = 0;
    for (int u = c; u < NUNIT; u += NCTA, ++w) {
        int mt = u >> 3, nt = u & 7;
        int m0 = mt * BM;
        int b  = mt >> 4;
        const __half* Ag = g_Xh + (size_t)m0 * Hd;
        const __half* Bg = g_Wt + (size_t)(nt * BN) * Hd;

        // wait until THIS unit's m-tile is fully converted (fine-grained)
        if (tid == 0) {
            volatile int* pc = &g_mcnt[mt];
            while (*pc < BM) { }
        }
        __syncthreads();

        // conversion duty for wave w+2: slice rows [crow, crow+16)
        int crow = WROWS * (w + 2) + 16 * c;
        bool conv = (crow < BS);
        int cbase4 = crow * 256;
        float4 cbuf;
        if (conv) cbuf = tok4[cbase4 + tid];     // prefetch element 0

        uint32_t acc[2][8][2];
        #pragma unroll
        for (int mq = 0; mq < 2; ++mq)
            #pragma unroll
            for (int j = 0; j < 8; ++j) {
                acc[mq][j][0] = 0u;
                acc[mq][j][1] = 0u;
            }

        #pragma unroll
        for (int q = 0; q < STG - 1; ++q) {
            int k0 = q * BKg;
            uint32_t base = sb + q * STAGE_BYTES;
            cpa16(base + lr * LDT + lc,            Ag + (size_t)lr * Hd + k0 + lck);
            cpa16(base + (lr + 64) * LDT + lc,     Ag + (size_t)(lr + 64) * Hd + k0 + lck);
            cpa16(base + A_SZ + lr * LDT + lc,        Bg + (size_t)lr * Hd + k0 + lck);
            cpa16(base + A_SZ + (lr + 64) * LDT + lc, Bg + (size_t)(lr + 64) * Hd + k0 + lck);
            cpa_commit();
        }

        for (int g = 0; g < 32; ++g) {
            CPA_WAIT2();
            __syncthreads();
            int q = g + STG - 1;
            if (q < 32) {
                int k0 = q * BKg;
                uint32_t base = sb + (q & 3) * STAGE_BYTES;
                cpa16(base + lr * LDT + lc,            Ag + (size_t)lr * Hd + k0 + lck);
                cpa16(base + (lr + 64) * LDT + lc,     Ag + (size_t)(lr + 64) * Hd + k0 + lck);
                cpa16(base + A_SZ + lr * LDT + lc,        Bg + (size_t)lr * Hd + k0 + lck);
                cpa16(base + A_SZ + (lr + 64) * LDT + lc, Bg + (size_t)(lr + 64) * Hd + k0 + lck);
            }
            cpa_commit();

            // pipelined conversion: STG element g (loaded at iter g-1),
            // prefetch element g+1. Dep distance = 1 chunk >> DRAM latency.
            if (conv && g < 16) {
                float4 nxt;
                if (g < 15) nxt = tok4[cbase4 + (g + 1) * 256 + tid];
                Xh4[cbase4 + g * 256 + tid] = cvt8(cbuf);
                if (g < 15) cbuf = nxt;
            }

            uint32_t ab = sb + (g & 3) * STAGE_BYTES;

            uint32_t a0[2][4], b0[4][4], a1[2][4], b1[4][4];
            LDSM4(a0[0], ab + aoff[0]);
            LDSM4(a0[1], ab + aoff[1]);
            #pragma unroll
            for (int jp = 0; jp < 4; ++jp) LDSM4(b0[jp], ab + boff[jp]);
            LDSM4(a1[0], ab + aoff[0] + 32);
            LDSM4(a1[1], ab + aoff[1] + 32);

            #pragma unroll
            for (int mq = 0; mq < 2; ++mq)
                #pragma unroll
                for (int j = 0; j < 8; ++j)
                    mma16816h(acc[mq][j], a0[mq], b0[j >> 1][(j & 1) * 2],
                              b0[j >> 1][(j & 1) * 2 + 1]);

            #pragma unroll
            for (int jp = 0; jp < 4; ++jp) LDSM4(b1[jp], ab + boff[jp] + 32);

            #pragma unroll
            for (int mq = 0; mq < 2; ++mq)
                #pragma unroll
                for (int j = 0; j < 8; ++j)
                    mma16816h(acc[mq][j], a1[mq], b1[j >> 1][(j & 1) * 2],
                              b1[j >> 1][(j & 1) * 2 + 1]);
        }

        // publish converted slice (its m-tile counter)
        if (conv) {
            __threadfence();
            __syncthreads();
            if (tid == 0) atomicAdd(&g_mcnt[crow >> 7], 16);
        }

        // epilogue: tanh + v-dot over this unit's 128 cols
        int nb = nt * BN + warpN * 64 + (lane & 3) * 2;
        float p[4] = {0.f, 0.f, 0.f, 0.f};
        #pragma unroll
        for (int j = 0; j < 8; ++j) {
            int n0e = nb + j * 8;
            float v0 = v[n0e],     c0 = g_cvec[b * Hd + n0e];
            float v1 = v[n0e + 1], c1 = g_cvec[b * Hd + n0e + 1];
            #pragma unroll
            for (int mq = 0; mq < 2; ++mq) {
                __half2 lo = *reinterpret_cast<__half2*>(&acc[mq][j][0]);
                __half2 hi = *reinterpret_cast<__half2*>(&acc[mq][j][1]);
                p[mq * 2 + 0] += v0 * fast_tanh(__low2float(lo) + c0)
                               + v1 * fast_tanh(__high2float(lo) + c1);
                p[mq * 2 + 1] += v0 * fast_tanh(__low2float(hi) + c0)
                               + v1 * fast_tanh(__high2float(hi) + c1);
            }
        }

        #pragma unroll
        for (int i = 0; i < 4; ++i) {
            p[i] += __shfl_xor_sync(0xFFFFFFFFu, p[i], 1);
            p[i] += __shfl_xor_sync(0xFFFFFFFFu, p[i], 2);
        }
        if ((lane & 3) == 0) {
            int part = nt * 2 + warpN;
            #pragma unroll
            for (int mq = 0; mq < 2; ++mq)
                #pragma unroll
                for (int rh = 0; rh < 2; ++rh) {
                    int row = warpM * 32 + mq * 16 + (lane >> 2) + rh * 8;
                    g_part[part * BS + m0 + row] = p[mq * 2 + rh];
                }
        }
    }
}

// ---------------------------------------------------------------------------
__global__ void softmax_kernel() {
    int b = blockIdx.x, tid = threadIdx.x;
    __shared__ float red[256];
    __shared__ float sc[Sd];

    for (int s = tid; s < Sd; s += 256) {
        int row = b * Sd + s;
        float t = 0.f;
        #pragma unroll
        for (int j = 0; j < 16; ++j)
            t += g_part[j * BS + row];
        sc[s] = t;
    }
    __syncthreads();

    float m = -1e30f;
    for (int s = tid; s < Sd; s += 256) m = fmaxf(m, sc[s]);
    red[tid] = m;
    __syncthreads();
    for (int o = 128; o > 0; o >>= 1) {
        if (tid < o) red[tid] = fmaxf(red[tid], red[tid + o]);
        __syncthreads();
    }
    float mx = red[0];
    __syncthreads();
    float sum = 0.f;
    for (int s = tid; s < Sd; s += 256) {
        float e = expf(sc[s] - mx);
        g_weights[b * Sd + s] = e;
        sum += e;
    }
    red[tid] = sum;
    __syncthreads();
    for (int o = 128; o > 0; o >>= 1) {
        if (tid < o) red[tid] += red[tid + o];
        __syncthreads();
    }
    float inv = 1.0f / red[0];
    for (int s = tid; s < Sd; s += 256)
        g_weights[b * Sd + s] *= inv;
}

__global__ void scale_kernel(const float* __restrict__ X, float* __restrict__ out,
                             int total4) {
    int idx = blockIdx.x * blockDim.x + threadIdx.x;
    int stride = gridDim.x * blockDim.x;
    for (int i = idx; i < total4; i += stride) {
        float w = 1.0f + g_weights[i >> 8];
        float4 t = ((const float4*)X)[i];
        t.x *= w; t.y *= w; t.z *= w; t.w *= w;
        ((float4*)out)[i] = t;
    }
}

// ---------------------------------------------------------------------------
extern "C" void kernel_launch(void* const* d_in, const int* in_sizes, int n_in,
                              void* d_out, int out_size) {
    const float* tok  = (const float*)d_in[0];
    const float* asp  = (const float*)d_in[1];
    const float* W    = (const float*)d_in[2];
    const float* bias = (const float*)d_in[3];
    const float* v    = (const float*)d_in[4];
    float* out = (float*)d_out;

    cudaFuncSetAttribute(gemm_score_mma, cudaFuncAttributeMaxDynamicSharedMemorySize,
                         SMEM_TOTAL);

    prep_kernel<<<1089, 256>>>(W, asp, bias);
    gemm_score_mma<<<NCTA, 256, SMEM_TOTAL>>>((const float4*)tok, v);
    softmax_kernel<<<Bd, 256>>>();
    scale_kernel<<<8192, 256>>>(tok, out, (Bd * Sd * Hd) / 4);
}

// round 15
// speedup vs baseline: 1.1829x; 1.1829x over previous
#include <cuda_runtime.h>
#include <cuda_fp16.h>
#include <stdint.h>
#include <math.h>

#define Hd 1024
#define Sd 2048
#define Bd 16
#define Ad 8
#define BS (Bd * Sd)          // 32768 rows

#define NCTA 444              // 148 SMs x 3
#define NUNIT 2048            // 256 m-tiles x 8 n-tiles
#define BM 128
#define BN 128
#define BKg 32
#define STG 3
#define LDT 80                          // padded row pitch bytes
#define A_SZ (BM * LDT)                 // 10240
#define STAGE_BYTES (2 * A_SZ)          // 20480
#define SMEM_TOTAL (STG * STAGE_BYTES)  // 61440 (x3 CTAs = 184KB/SM)

// ---------------------------------------------------------------------------
__device__ __half g_Xh[(size_t)BS * Hd];        // 64 MB fp16 X
__device__ __half g_Wt[(size_t)Hd * Hd];        // W1^T: [N][K], fp16
__device__ float g_cvec[Bd * Hd];
__device__ float g_part[16 * BS];               // 2 MB partial scores
__device__ float g_weights[Bd * Sd];

// ---------------------------------------------------------------------------
__device__ __forceinline__ uint32_t smem_u32(const void* p) {
    uint32_t a;
    asm("{ .reg .u64 t; cvta.to.shared.u64 t, %1; cvt.u32.u64 %0, t; }" : "=r"(a) : "l"(p));
    return a;
}
__device__ __forceinline__ void cpa16(uint32_t dst, const void* src) {
    asm volatile("cp.async.cg.shared.global [%0], [%1], 16;" :: "r"(dst), "l"(src));
}
__device__ __forceinline__ void cpa_commit() {
    asm volatile("cp.async.commit_group;" ::: "memory");
}
#define CPA_WAIT1() asm volatile("cp.async.wait_group 1;" ::: "memory")
#define LDSM4(r, addr)                                                        \
    asm volatile("ldmatrix.sync.aligned.m8n8.x4.shared.b16 {%0,%1,%2,%3}, [%4];" \
        : "=r"((r)[0]), "=r"((r)[1]), "=r"((r)[2]), "=r"((r)[3]) : "r"(addr))
__device__ __forceinline__ void mma16816h(uint32_t* d, const uint32_t* a,
                                          uint32_t b0, uint32_t b1) {
    asm volatile(
        "mma.sync.aligned.m16n8k16.row.col.f16.f16.f16.f16 "
        "{%0,%1}, {%2,%3,%4,%5}, {%6,%7}, {%0,%1};"
        : "+r"(d[0]), "+r"(d[1])
        : "r"(a[0]), "r"(a[1]), "r"(a[2]), "r"(a[3]), "r"(b0), "r"(b1));
}
__device__ __forceinline__ float fast_tanh(float x) {
    float y;
    asm("tanh.approx.f32 %0, %1;" : "=f"(y) : "f"(x));
    return y;
}

// ---------------------------------------------------------------------------
// Fused prep: [0,4096) convert X->fp16; [4096,5120) transpose W1; rest cvec.
// ---------------------------------------------------------------------------
__global__ void prep_kernel(const float4* __restrict__ X4,
                            const float* __restrict__ W,
                            const float* __restrict__ aspect,
                            const float* __restrict__ bias) {
    int bi = blockIdx.x, tid = threadIdx.x;
    if (bi < 4096) {
        int n4 = BS * Hd / 4;
        for (int i = bi * 256 + tid; i < n4; i += 4096 * 256) {
            float4 v = X4[i];
            __half2 lo = __floats2half2_rn(v.x, v.y);
            __half2 hi = __floats2half2_rn(v.z, v.w);
            uint2 pk;
            pk.x = *reinterpret_cast<uint32_t*>(&lo);
            pk.y = *reinterpret_cast<uint32_t*>(&hi);
            reinterpret_cast<uint2*>(g_Xh)[i] = pk;
        }
    } else if (bi < 5120) {
        __shared__ float t[32][33];
        int q = bi - 4096;
        int n0 = (q & 31) * 32, k0 = (q >> 5) * 32;
        int tx = tid & 31, ty = tid >> 5;            // 32 x 8
        #pragma unroll
        for (int i = 0; i < 32; i += 8)
            t[ty + i][tx] = W[(size_t)(k0 + ty + i) * Hd + n0 + tx];
        __syncthreads();
        #pragma unroll
        for (int i = 0; i < 32; i += 8)
            g_Wt[(size_t)(n0 + ty + i) * Hd + k0 + tx] = __float2half(t[tx][ty + i]);
    } else {
        __shared__ float asp[Hd];
        int q = bi - 5120;
        int b = q & 15, hb = q >> 4;
        for (int k = tid; k < Hd; k += 256) {
            float s = 0.f;
            #pragma unroll
            for (int a = 0; a < Ad; ++a)
                s += aspect[(size_t)(b * Ad + a) * Hd + k];
            asp[k] = s * (1.0f / Ad);
        }
        __syncthreads();
        int h = hb * 256 + tid;
        float acc = bias[h];
        const float* Wp = W + (size_t)Hd * Hd + h;
        #pragma unroll 8
        for (int k = 0; k < Hd; ++k)
            acc = fmaf(asp[k], Wp[(size_t)k * Hd], acc);
        g_cvec[b * Hd + h] = acc;
    }
}

// ---------------------------------------------------------------------------
// Persistent fused GEMM + tanh + v-dot -> g_part.
// 3 CTAs/SM (6 warps/SMSP) for bubble hiding; fp16 accum; register-lean
// unstaggered inner loop; 3-stage cp.async.
// ---------------------------------------------------------------------------
__global__ void __launch_bounds__(256, 3)
gemm_score_mma(const float* __restrict__ v) {
    extern __shared__ char smem[];
    uint32_t sb = smem_u32(smem);

    int tid = threadIdx.x, lane = tid & 31, wid = tid >> 5;
    int warpM = wid & 3, warpN = wid >> 2;

    uint32_t aoff[2], boff[4];
    #pragma unroll
    for (int mt = 0; mt < 2; ++mt) {
        int r = warpM * 32 + mt * 16 + ((lane >> 3) & 1) * 8 + (lane & 7);
        aoff[mt] = r * LDT + (lane >> 4) * 16;
    }
    #pragma unroll
    for (int jp = 0; jp < 4; ++jp) {
        int n = warpN * 64 + (jp * 2 + (lane >> 4)) * 8 + (lane & 7);
        boff[jp] = A_SZ + n * LDT + ((lane >> 3) & 1) * 16;
    }

    int lr  = tid >> 2;
    int lc  = (tid & 3) * 16;
    int lck = (tid & 3) * 8;

    for (int u = blockIdx.x; u < NUNIT; u += NCTA) {
        int mt = u >> 3, nt = u & 7;
        int m0 = mt * BM;
        int b  = mt >> 4;
        const __half* Ag = g_Xh + (size_t)m0 * Hd;
        const __half* Bg = g_Wt + (size_t)(nt * BN) * Hd;

        uint32_t acc[2][8][2];
        #pragma unroll
        for (int mq = 0; mq < 2; ++mq)
            #pragma unroll
            for (int j = 0; j < 8; ++j) {
                acc[mq][j][0] = 0u;
                acc[mq][j][1] = 0u;
            }

        // prologue: chunks 0,1
        #pragma unroll
        for (int q = 0; q < STG - 1; ++q) {
            int k0 = q * BKg;
            uint32_t base = sb + q * STAGE_BYTES;
            cpa16(base + lr * LDT + lc,            Ag + (size_t)lr * Hd + k0 + lck);
            cpa16(base + (lr + 64) * LDT + lc,     Ag + (size_t)(lr + 64) * Hd + k0 + lck);
            cpa16(base + A_SZ + lr * LDT + lc,        Bg + (size_t)lr * Hd + k0 + lck);
            cpa16(base + A_SZ + (lr + 64) * LDT + lc, Bg + (size_t)(lr + 64) * Hd + k0 + lck);
            cpa_commit();
        }

        for (int g = 0; g < 32; ++g) {
            CPA_WAIT1();       // chunk g complete (this thread)
            __syncthreads();   // publish chunk g; fences reuse of slot (g+2)%3
            int q = g + STG - 1;
            if (q < 32) {
                int k0 = q * BKg;
                uint32_t base = sb + (q % 3) * STAGE_BYTES;
                cpa16(base + lr * LDT + lc,            Ag + (size_t)lr * Hd + k0 + lck);
                cpa16(base + (lr + 64) * LDT + lc,     Ag + (size_t)(lr + 64) * Hd + k0 + lck);
                cpa16(base + A_SZ + lr * LDT + lc,        Bg + (size_t)lr * Hd + k0 + lck);
                cpa16(base + A_SZ + (lr + 64) * LDT + lc, Bg + (size_t)(lr + 64) * Hd + k0 + lck);
            }
            cpa_commit();      // unconditional: exact wait accounting at tail

            uint32_t ab = sb + (g % 3) * STAGE_BYTES;

            // simple (register-lean) k-step loop: 24 fragment regs live
            #pragma unroll
            for (int ks = 0; ks < 2; ++ks) {
                uint32_t koff = ks * 32;
                uint32_t af[2][4], bf[4][4];
                LDSM4(af[0], ab + aoff[0] + koff);
                LDSM4(af[1], ab + aoff[1] + koff);
                #pragma unroll
                for (int jp = 0; jp < 4; ++jp) LDSM4(bf[jp], ab + boff[jp] + koff);
                #pragma unroll
                for (int mq = 0; mq < 2; ++mq)
                    #pragma unroll
                    for (int j = 0; j < 8; ++j)
                        mma16816h(acc[mq][j], af[mq], bf[j >> 1][(j & 1) * 2],
                                  bf[j >> 1][(j & 1) * 2 + 1]);
            }
        }

        // epilogue: tanh + v-dot over this unit's 128 cols
        int nb = nt * BN + warpN * 64 + (lane & 3) * 2;
        float p[4] = {0.f, 0.f, 0.f, 0.f};
        #pragma unroll
        for (int j = 0; j < 8; ++j) {
            int n0e = nb + j * 8;
            float v0 = v[n0e],     c0 = g_cvec[b * Hd + n0e];
            float v1 = v[n0e + 1], c1 = g_cvec[b * Hd + n0e + 1];
            #pragma unroll
            for (int mq = 0; mq < 2; ++mq) {
                __half2 lo = *reinterpret_cast<__half2*>(&acc[mq][j][0]);
                __half2 hi = *reinterpret_cast<__half2*>(&acc[mq][j][1]);
                p[mq * 2 + 0] += v0 * fast_tanh(__low2float(lo) + c0)
                               + v1 * fast_tanh(__high2float(lo) + c1);
                p[mq * 2 + 1] += v0 * fast_tanh(__low2float(hi) + c0)
                               + v1 * fast_tanh(__high2float(hi) + c1);
            }
        }

        #pragma unroll
        for (int i = 0; i < 4; ++i) {
            p[i] += __shfl_xor_sync(0xFFFFFFFFu, p[i], 1);
            p[i] += __shfl_xor_sync(0xFFFFFFFFu, p[i], 2);
        }
        if ((lane & 3) == 0) {
            int part = nt * 2 + warpN;
            #pragma unroll
            for (int mq = 0; mq < 2; ++mq)
                #pragma unroll
                for (int rh = 0; rh < 2; ++rh) {
                    int row = warpM * 32 + mq * 16 + (lane >> 2) + rh * 8;
                    g_part[part * BS + m0 + row] = p[mq * 2 + rh];
                }
        }
        __syncthreads();   // chunk-31 readers (slots 0,1) finish before next
                           // unit's prologue overwrites those slots
    }
}

// ---------------------------------------------------------------------------
__global__ void softmax_kernel() {
    int b = blockIdx.x, tid = threadIdx.x;
    __shared__ float red[256];
    __shared__ float sc[Sd];

    for (int s = tid; s < Sd; s += 256) {
        int row = b * Sd + s;
        float t = 0.f;
        #pragma unroll
        for (int j = 0; j < 16; ++j)
            t += g_part[j * BS + row];
        sc[s] = t;
    }
    __syncthreads();

    float m = -1e30f;
    for (int s = tid; s < Sd; s += 256) m = fmaxf(m, sc[s]);
    red[tid] = m;
    __syncthreads();
    for (int o = 128; o > 0; o >>= 1) {
        if (tid < o) red[tid] = fmaxf(red[tid], red[tid + o]);
        __syncthreads();
    }
    float mx = red[0];
    __syncthreads();
    float sum = 0.f;
    for (int s = tid; s < Sd; s += 256) {
        float e = expf(sc[s] - mx);
        g_weights[b * Sd + s] = e;
        sum += e;
    }
    red[tid] = sum;
    __syncthreads();
    for (int o = 128; o > 0; o >>= 1) {
        if (tid < o) red[tid] += red[tid + o];
        __syncthreads();
    }
    float inv = 1.0f / red[0];
    for (int s = tid; s < Sd; s += 256)
        g_weights[b * Sd + s] *= inv;
}

__global__ void scale_kernel(const float* __restrict__ X, float* __restrict__ out,
                             int total4) {
    int idx = blockIdx.x * blockDim.x + threadIdx.x;
    int stride = gridDim.x * blockDim.x;
    for (int i = idx; i < total4; i += stride) {
        float w = 1.0f + g_weights[i >> 8];
        float4 t = ((const float4*)X)[i];
        t.x *= w; t.y *= w; t.z *= w; t.w *= w;
        ((float4*)out)[i] = t;
    }
}

// ---------------------------------------------------------------------------
extern "C" void kernel_launch(void* const* d_in, const int* in_sizes, int n_in,
                              void* d_out, int out_size) {
    const float* tok  = (const float*)d_in[0];
    const float* asp  = (const float*)d_in[1];
    const float* W    = (const float*)d_in[2];
    const float* bias = (const float*)d_in[3];
    const float* v    = (const float*)d_in[4];
    float* out = (float*)d_out;

    cudaFuncSetAttribute(gemm_score_mma, cudaFuncAttributeMaxDynamicSharedMemorySize,
                         SMEM_TOTAL);

    prep_kernel<<<5184, 256>>>((const float4*)tok, W, asp, bias);
    gemm_score_mma<<<NCTA, 256, SMEM_TOTAL>>>(v);
    softmax_kernel<<<Bd, 256>>>();
    scale_kernel<<<8192, 256>>>(tok, out, (Bd * Sd * Hd) / 4);
}

// round 17
// speedup vs baseline: 1.6333x; 1.3808x over previous
#include <cuda_runtime.h>
#include <cuda_bf16.h>
#include <stdint.h>
#include <math.h>

#define Hd 1024
#define Sd 2048
#define Bd 16
#define Ad 8
#define BS (Bd * Sd)          // 32768 rows

#define NCTA 296              // 148 SMs x 2
#define NUNIT 2048            // 256 m-tiles x 8 n-tiles
#define BM 128
#define BN 128
#define BKg 32
#define STG 4
#define LDT 80                          // padded row pitch bytes
#define A_SZ (BM * LDT)                 // 10240
#define STAGE_BYTES (2 * A_SZ)          // 20480
#define SMEM_TOTAL (STG * STAGE_BYTES)  // 81920 (x2 CTAs = 164KB/SM)

// ---------------------------------------------------------------------------
__device__ __nv_bfloat16 g_Xbf[(size_t)BS * Hd];       // 64 MB
__device__ __nv_bfloat16 g_Wt[(size_t)Hd * Hd];        // W1^T: [N][K]
__device__ float g_cvec[Bd * Hd];
__device__ float g_part[16 * BS];                      // 2 MB partial scores
__device__ float g_weights[Bd * Sd];

// ---------------------------------------------------------------------------
__device__ __forceinline__ uint32_t smem_u32(const void* p) {
    uint32_t a;
    asm("{ .reg .u64 t; cvta.to.shared.u64 t, %1; cvt.u32.u64 %0, t; }" : "=r"(a) : "l"(p));
    return a;
}
__device__ __forceinline__ void cpa16(uint32_t dst, const void* src) {
    asm volatile("cp.async.cg.shared.global [%0], [%1], 16;" :: "r"(dst), "l"(src));
}
__device__ __forceinline__ void cpa_commit() {
    asm volatile("cp.async.commit_group;" ::: "memory");
}
#define CPA_WAIT2() asm volatile("cp.async.wait_group 2;" ::: "memory")
#define LDSM4(r, addr)                                                        \
    asm volatile("ldmatrix.sync.aligned.m8n8.x4.shared.b16 {%0,%1,%2,%3}, [%4];" \
        : "=r"((r)[0]), "=r"((r)[1]), "=r"((r)[2]), "=r"((r)[3]) : "r"(addr))
__device__ __forceinline__ void mma16816(float* d, const uint32_t* a,
                                         uint32_t b0, uint32_t b1) {
    asm volatile(
        "mma.sync.aligned.m16n8k16.row.col.f32.bf16.bf16.f32 "
        "{%0,%1,%2,%3}, {%4,%5,%6,%7}, {%8,%9}, {%0,%1,%2,%3};"
        : "+f"(d[0]), "+f"(d[1]), "+f"(d[2]), "+f"(d[3])
        : "r"(a[0]), "r"(a[1]), "r"(a[2]), "r"(a[3]), "r"(b0), "r"(b1));
}
__device__ __forceinline__ float fast_tanh(float x) {
    float y;
    asm("tanh.approx.f32 %0, %1;" : "=f"(y) : "f"(x));
    return y;
}
__device__ __forceinline__ void stg_cs_u2(void* p, uint2 val) {
    asm volatile("st.global.cs.v2.u32 [%0], {%1, %2};" :: "l"(p), "r"(val.x), "r"(val.y));
}
__device__ __forceinline__ void stg_cs_f4(void* p, float4 t) {
    asm volatile("st.global.cs.v4.f32 [%0], {%1, %2, %3, %4};"
                 :: "l"(p), "f"(t.x), "f"(t.y), "f"(t.z), "f"(t.w));
}

// ---------------------------------------------------------------------------
// Fused prep: [0,4096) convert X; [4096,5120) transpose W1; [5120,5184) cvec.
// ---------------------------------------------------------------------------
__global__ void prep_kernel(const float4* __restrict__ X4,
                            const float* __restrict__ W,
                            const float* __restrict__ aspect,
                            const float* __restrict__ bias) {
    int bi = blockIdx.x, tid = threadIdx.x;
    if (bi < 4096) {
        int n4 = BS * Hd / 4;
        for (int i = bi * 256 + tid; i < n4; i += 4096 * 256) {
            float4 v = X4[i];
            __nv_bfloat162 lo = __floats2bfloat162_rn(v.x, v.y);
            __nv_bfloat162 hi = __floats2bfloat162_rn(v.z, v.w);
            uint2 pk;
            pk.x = *reinterpret_cast<uint32_t*>(&lo);
            pk.y = *reinterpret_cast<uint32_t*>(&hi);
            stg_cs_u2(reinterpret_cast<uint2*>(g_Xbf) + i, pk);  // streaming
        }
    } else if (bi < 5120) {
        __shared__ float t[32][33];
        int q = bi - 4096;
        int n0 = (q & 31) * 32, k0 = (q >> 5) * 32;
        int tx = tid & 31, ty = tid >> 5;            // 32 x 8
        #pragma unroll
        for (int i = 0; i < 32; i += 8)
            t[ty + i][tx] = W[(size_t)(k0 + ty + i) * Hd + n0 + tx];
        __syncthreads();
        #pragma unroll
        for (int i = 0; i < 32; i += 8)
            g_Wt[(size_t)(n0 + ty + i) * Hd + k0 + tx] = __float2bfloat16(t[tx][ty + i]);
    } else {
        __shared__ float asp[Hd];
        int q = bi - 5120;
        int b = q & 15, hb = q >> 4;
        for (int k = tid; k < Hd; k += 256) {
            float s = 0.f;
            #pragma unroll
            for (int a = 0; a < Ad; ++a)
                s += aspect[(size_t)(b * Ad + a) * Hd + k];
            asp[k] = s * (1.0f / Ad);
        }
        __syncthreads();
        int h = hb * 256 + tid;
        float acc = bias[h];
        const float* Wp = W + (size_t)Hd * Hd + h;
        #pragma unroll 8
        for (int k = 0; k < Hd; ++k)
            acc = fmaf(asp[k], Wp[(size_t)k * Hd], acc);
        g_cvec[b * Hd + h] = acc;
    }
}

// ---------------------------------------------------------------------------
// Persistent fused GEMM + tanh + v-dot -> g_part. (R8 core, unchanged.)
// 296 CTAs; unit u = (mt, nt): 128 x 128 x K=1024; 8 warps 4(M)x2(N).
// ---------------------------------------------------------------------------
__global__ void __launch_bounds__(256, 2)
gemm_score_mma(const float* __restrict__ v) {
    extern __shared__ char smem[];
    uint32_t sb = smem_u32(smem);

    int tid = threadIdx.x, lane = tid & 31, wid = tid >> 5;
    int warpM = wid & 3, warpN = wid >> 2;

    uint32_t aoff[2], boff[4];
    #pragma unroll
    for (int mt = 0; mt < 2; ++mt) {
        int r = warpM * 32 + mt * 16 + ((lane >> 3) & 1) * 8 + (lane & 7);
        aoff[mt] = r * LDT + (lane >> 4) * 16;
    }
    #pragma unroll
    for (int jp = 0; jp < 4; ++jp) {
        int n = warpN * 64 + (jp * 2 + (lane >> 4)) * 8 + (lane & 7);
        boff[jp] = A_SZ + n * LDT + ((lane >> 3) & 1) * 16;
    }

    int lr  = tid >> 2;
    int lc  = (tid & 3) * 16;
    int lck = (tid & 3) * 8;

    for (int u = blockIdx.x; u < NUNIT; u += NCTA) {
        int mt = u >> 3, nt = u & 7;
        int m0 = mt * BM;
        int b  = mt >> 4;
        const __nv_bfloat16* Ag = g_Xbf + (size_t)m0 * Hd;
        const __nv_bfloat16* Bg = g_Wt + (size_t)(nt * BN) * Hd;

        float acc[2][8][4];
        #pragma unroll
        for (int mq = 0; mq < 2; ++mq)
            #pragma unroll
            for (int j = 0; j < 8; ++j)
                #pragma unroll
                for (int e = 0; e < 4; ++e) acc[mq][j][e] = 0.f;

        #pragma unroll
        for (int q = 0; q < STG - 1; ++q) {
            int k0 = q * BKg;
            uint32_t base = sb + q * STAGE_BYTES;
            cpa16(base + lr * LDT + lc,            Ag + (size_t)lr * Hd + k0 + lck);
            cpa16(base + (lr + 64) * LDT + lc,     Ag + (size_t)(lr + 64) * Hd + k0 + lck);
            cpa16(base + A_SZ + lr * LDT + lc,        Bg + (size_t)lr * Hd + k0 + lck);
            cpa16(base + A_SZ + (lr + 64) * LDT + lc, Bg + (size_t)(lr + 64) * Hd + k0 + lck);
            cpa_commit();
        }

        for (int g = 0; g < 32; ++g) {
            CPA_WAIT2();
            __syncthreads();
            int q = g + STG - 1;
            if (q < 32) {
                int k0 = q * BKg;
                uint32_t base = sb + (q & 3) * STAGE_BYTES;
                cpa16(base + lr * LDT + lc,            Ag + (size_t)lr * Hd + k0 + lck);
                cpa16(base + (lr + 64) * LDT + lc,     Ag + (size_t)(lr + 64) * Hd + k0 + lck);
                cpa16(base + A_SZ + lr * LDT + lc,        Bg + (size_t)lr * Hd + k0 + lck);
                cpa16(base + A_SZ + (lr + 64) * LDT + lc, Bg + (size_t)(lr + 64) * Hd + k0 + lck);
            }
            cpa_commit();

            uint32_t ab = sb + (g & 3) * STAGE_BYTES;

            uint32_t a0[2][4], b0[4][4], a1[2][4], b1[4][4];
            LDSM4(a0[0], ab + aoff[0]);
            LDSM4(a0[1], ab + aoff[1]);
            #pragma unroll
            for (int jp = 0; jp < 4; ++jp) LDSM4(b0[jp], ab + boff[jp]);
            LDSM4(a1[0], ab + aoff[0] + 32);
            LDSM4(a1[1], ab + aoff[1] + 32);

            #pragma unroll
            for (int mq = 0; mq < 2; ++mq)
                #pragma unroll
                for (int j = 0; j < 8; ++j)
                    mma16816(acc[mq][j], a0[mq], b0[j >> 1][(j & 1) * 2],
                             b0[j >> 1][(j & 1) * 2 + 1]);

            #pragma unroll
            for (int jp = 0; jp < 4; ++jp) LDSM4(b1[jp], ab + boff[jp] + 32);

            #pragma unroll
            for (int mq = 0; mq < 2; ++mq)
                #pragma unroll
                for (int j = 0; j < 8; ++j)
                    mma16816(acc[mq][j], a1[mq], b1[j >> 1][(j & 1) * 2],
                             b1[j >> 1][(j & 1) * 2 + 1]);
        }

        // epilogue: tanh + v-dot over this unit's 128 cols
        int nb = nt * BN + warpN * 64 + (lane & 3) * 2;
        float vv[16], cv[16];
        #pragma unroll
        for (int j = 0; j < 8; ++j)
            #pragma unroll
            for (int h = 0; h < 2; ++h) {
                int n = nb + j * 8 + h;
                vv[j * 2 + h] = v[n];
                cv[j * 2 + h] = g_cvec[b * Hd + n];
            }

        float p[4] = {0.f, 0.f, 0.f, 0.f};
        #pragma unroll
        for (int mq = 0; mq < 2; ++mq)
            #pragma unroll
            for (int j = 0; j < 8; ++j)
                #pragma unroll
                for (int e = 0; e < 4; ++e) {
                    int h = e & 1, rh = e >> 1;
                    float x = acc[mq][j][e] + cv[j * 2 + h];
                    p[mq * 2 + rh] += vv[j * 2 + h] * fast_tanh(x);
                }

        #pragma unroll
        for (int i = 0; i < 4; ++i) {
            p[i] += __shfl_xor_sync(0xFFFFFFFFu, p[i], 1);
            p[i] += __shfl_xor_sync(0xFFFFFFFFu, p[i], 2);
        }
        if ((lane & 3) == 0) {
            int part = nt * 2 + warpN;
            #pragma unroll
            for (int mq = 0; mq < 2; ++mq)
                #pragma unroll
                for (int rh = 0; rh < 2; ++rh) {
                    int row = warpM * 32 + mq * 16 + (lane >> 2) + rh * 8;
                    g_part[part * BS + m0 + row] = p[mq * 2 + rh];
                }
        }
    }
}

// ---------------------------------------------------------------------------
__global__ void softmax_kernel() {
    int b = blockIdx.x, tid = threadIdx.x;
    __shared__ float red[256];
    __shared__ float sc[Sd];

    for (int s = tid; s < Sd; s += 256) {
        int row = b * Sd + s;
        float t = 0.f;
        #pragma unroll
        for (int j = 0; j < 16; ++j)
            t += g_part[j * BS + row];
        sc[s] = t;
    }
    __syncthreads();

    float m = -1e30f;
    for (int s = tid; s < Sd; s += 256) m = fmaxf(m, sc[s]);
    red[tid] = m;
    __syncthreads();
    for (int o = 128; o > 0; o >>= 1) {
        if (tid < o) red[tid] = fmaxf(red[tid], red[tid + o]);
        __syncthreads();
    }
    float mx = red[0];
    __syncthreads();
    float sum = 0.f;
    for (int s = tid; s < Sd; s += 256) {
        float e = expf(sc[s] - mx);
        g_weights[b * Sd + s] = e;
        sum += e;
    }
    red[tid] = sum;
    __syncthreads();
    for (int o = 128; o > 0; o >>= 1) {
        if (tid < o) red[tid] += red[tid + o];
        __syncthreads();
    }
    float inv = 1.0f / red[0];
    for (int s = tid; s < Sd; s += 256)
        g_weights[b * Sd + s] *= inv;
}

// ---------------------------------------------------------------------------
// scale: 2x ILP (independent loads) + streaming stores.
// ---------------------------------------------------------------------------
__global__ void scale_kernel(const float* __restrict__ X, float* __restrict__ out,
                             int total4) {
    int idx = blockIdx.x * blockDim.x + threadIdx.x;
    int stride = gridDim.x * blockDim.x;
    for (int i = idx; i < (total4 >> 1); i += stride) {
        int i0 = i;                    // first half
        int i1 = i + (total4 >> 1);    // second half (independent)
        float4 t0 = ((const float4*)X)[i0];
        float4 t1 = ((const float4*)X)[i1];
        float w0 = 1.0f + g_weights[i0 >> 8];
        float w1 = 1.0f + g_weights[i1 >> 8];
        t0.x *= w0; t0.y *= w0; t0.z *= w0; t0.w *= w0;
        t1.x *= w1; t1.y *= w1; t1.z *= w1; t1.w *= w1;
        stg_cs_f4((float4*)out + i0, t0);
        stg_cs_f4((float4*)out + i1, t1);
    }
}

// ---------------------------------------------------------------------------
extern "C" void kernel_launch(void* const* d_in, const int* in_sizes, int n_in,
                              void* d_out, int out_size) {
    const float* tok  = (const float*)d_in[0];
    const float* asp  = (const float*)d_in[1];
    const float* W    = (const float*)d_in[2];
    const float* bias = (const float*)d_in[3];
    const float* v    = (const float*)d_in[4];
    float* out = (float*)d_out;

    cudaFuncSetAttribute(gemm_score_mma, cudaFuncAttributeMaxDynamicSharedMemorySize,
                         SMEM_TOTAL);

    prep_kernel<<<5184, 256>>>((const float4*)tok, W, asp, bias);
    gemm_score_mma<<<NCTA, 256, SMEM_TOTAL>>>(v);
    softmax_kernel<<<Bd, 256>>>();
    scale_kernel<<<4096, 256>>>(tok, out, (Bd * Sd * Hd) / 4);
}